// round 16
// baseline (speedup 1.0000x reference)
#include <cuda_runtime.h>
#include <cuda_bf16.h>
#include <cstdint>

// VectorQuantizer: N=262144 rows, D=64, K=1024 codes, fp32.
//
// Round 16 == Round 15 resubmit (R15 never ran: 4th broker/container infra
// failure; precedent R4/R9 — resubmit verbatim, kernel not implicated).
//
// SINGLE sweep, attempt 4 — every prior failure addressed:
//   R13 poison (branchy per-tile capture) -> unconditional group-min fold,
//     2 shfl + 1 STS per row per 64-code group (every 8 tiles), branch-free.
//   R6 poison (divergent rescore) -> R7's warp-cooperative rescore (validated):
//     warp/row, lane/code, ballot-selected groups.
//   R7 context (occ 1) -> R14's occ-3 streaming sweep.
// No candidate lists / atomics / overflow path: group capture is complete by
// construction. Sweep B deleted entirely.
// Exact selection (validated, bit-identical): M = serial ascending-d fmaf
// chain, t = Sx + Se, d = fmaf(-2, M, t), argmin strict < ascending k
// (lower index wins ties). Sx per row precomputed with the identical chain.

#define VQ_N       262144
#define VQ_D       64
#define VQ_K       1024
#define VQ_TPB     256
#define VQ_ROWS_PB 256                    // 8 warps x 32 rows
#define VQ_GRID    (VQ_N / VQ_ROWS_PB)   // 1024 blocks
#define VQ_EPAD    72                    // padded bf16 row (144B)
#define VQ_CHUNK   128                   // codes per pipeline stage
#define VQ_NCHUNK  (VQ_K / VQ_CHUNK)     // 8
#define VQ_GRP     64                    // codes per capture group
#define VQ_NGRP    (VQ_K / VQ_GRP)       // 16 groups
#define VQ_MARGIN  1e-3f

#define VQ_CHUNK_B (VQ_CHUNK * VQ_EPAD * 2)   // 18432 bytes per stage
#define VQ_SMEM_E  (2 * VQ_CHUNK_B)           // 36864 bytes dynamic

__device__ __nv_bfloat16 g_cbh[VQ_K * VQ_EPAD];
__device__ float         g_Se[VQ_K];
__device__ float         g_vq_partial[VQ_GRID];
__device__ unsigned int  g_vq_ticket;

__device__ __forceinline__ uint32_t pack_bf16x2(float lo, float hi) {
    __nv_bfloat162 h = __float22bfloat162_rn(make_float2(lo, hi));
    return *reinterpret_cast<uint32_t*>(&h);
}

__device__ __forceinline__ void mma_bf16(float& c0, float& c1, float& c2, float& c3,
                                         uint32_t a0, uint32_t a1, uint32_t a2, uint32_t a3,
                                         uint32_t b0, uint32_t b1) {
    asm volatile(
        "mma.sync.aligned.m16n8k16.row.col.f32.bf16.bf16.f32 "
        "{%0,%1,%2,%3},{%4,%5,%6,%7},{%8,%9},{%0,%1,%2,%3};"
        : "+f"(c0), "+f"(c1), "+f"(c2), "+f"(c3)
        : "r"(a0), "r"(a1), "r"(a2), "r"(a3), "r"(b0), "r"(b1));
}

__device__ __forceinline__ void ldsm_x4(uint32_t& r0, uint32_t& r1, uint32_t& r2, uint32_t& r3,
                                        uint32_t addr) {
    asm volatile("ldmatrix.sync.aligned.m8n8.x4.shared.b16 {%0,%1,%2,%3}, [%4];"
                 : "=r"(r0), "=r"(r1), "=r"(r2), "=r"(r3) : "r"(addr));
}

__device__ __forceinline__ void cp_async16(uint32_t dst_smem, const void* src) {
    asm volatile("cp.async.cg.shared.global [%0], [%1], 16;"
                 :: "r"(dst_smem), "l"(src));
}
__device__ __forceinline__ void cp_commit() { asm volatile("cp.async.commit_group;"); }
__device__ __forceinline__ void cp_wait1()  { asm volatile("cp.async.wait_group 1;"); }
__device__ __forceinline__ void cp_wait0()  { asm volatile("cp.async.wait_group 0;"); }

// Exact reference-rounding distance, streaming x from L1 (broadcast loads).
__device__ __forceinline__ float exact_dist_stream(const float4* __restrict__ xp, float Sx,
                                                   const float* __restrict__ cb,
                                                   const float* __restrict__ se, int idx) {
    const float4* e4 = reinterpret_cast<const float4*>(cb + (size_t)idx * VQ_D);
    float m = 0.0f;
    #pragma unroll
    for (int i = 0; i < VQ_D / 4; i++) {
        float4 q = e4[i], xv = xp[i];
        m = fmaf(xv.x, q.x, m); m = fmaf(xv.y, q.y, m);
        m = fmaf(xv.z, q.z, m); m = fmaf(xv.w, q.w, m);
    }
    float t = Sx + se[idx];
    return fmaf(-2.0f, m, t);
}

__global__ void vq_prep_kernel(const float* __restrict__ cb)
{
    int code = blockIdx.x * blockDim.x + threadIdx.x;
    if (code < VQ_K) {
        const float4* e4 = reinterpret_cast<const float4*>(cb + (size_t)code * VQ_D);
        uint32_t* dst = reinterpret_cast<uint32_t*>(g_cbh + code * VQ_EPAD);
        float s = 0.0f;
        #pragma unroll
        for (int i = 0; i < VQ_D / 4; i++) {
            float4 q = e4[i];
            s = fmaf(q.x, q.x, s); s = fmaf(q.y, q.y, s);
            s = fmaf(q.z, q.z, s); s = fmaf(q.w, q.w, s);
            dst[2 * i]     = pack_bf16x2(q.x, q.y);
            dst[2 * i + 1] = pack_bf16x2(q.z, q.w);
        }
        g_Se[code] = s;
    }
}

extern __shared__ __nv_bfloat16 s_stage[];   // 2 x VQ_CHUNK_B

__device__ __forceinline__ void copy_chunk(int ch, uint32_t s_base, int tid) {
    const char* src = reinterpret_cast<const char*>(g_cbh) + (size_t)ch * VQ_CHUNK_B;
    uint32_t dst = s_base + (uint32_t)((ch & 1) * VQ_CHUNK_B);
    #pragma unroll
    for (int i = tid; i < VQ_CHUNK_B / 16; i += VQ_TPB)
        cp_async16(dst + (uint32_t)(i * 16), src + i * 16);
    cp_commit();
}

__global__ void __launch_bounds__(VQ_TPB, 3)
vq_main_kernel(const float* __restrict__ x,
               const float* __restrict__ cb,
               float* __restrict__ out,
               int write_q, long long out_size)
{
    __shared__ float  s_Se[VQ_K];                       // 4 KB
    __shared__ float  s_gmin[VQ_NGRP][VQ_ROWS_PB + 1];  // 16.4 KB, pad=conflict-free
    __shared__ float  s_Sx[VQ_ROWS_PB];                 // 1 KB
    __shared__ int    s_win[VQ_ROWS_PB];                // 1 KB
    __shared__ float  s_red[VQ_TPB];                    // 1 KB
    __shared__ int    s_last;
    __shared__ double s_dred[VQ_TPB];                   // 2 KB

    const int tid  = threadIdx.x;
    const int wid  = tid >> 5;
    const int lane = tid & 31;
    const int g    = lane >> 2;
    const int tg   = lane & 3;
    const int rowbase = blockIdx.x * VQ_ROWS_PB;
    const int r0 = wid * 32 + g;
    const int r1 = r0 + 8;
    const int r2 = r0 + 16;
    const int r3 = r0 + 24;

    #pragma unroll
    for (int c = 0; c < VQ_K / VQ_TPB; c++)
        s_Se[tid + c * VQ_TPB] = g_Se[tid + c * VQ_TPB];

    // exact Sx per row (identical serial ascending fmaf chain)
    {
        const float4* xp = reinterpret_cast<const float4*>(x + (size_t)(rowbase + tid) * VQ_D);
        float s = 0.0f;
        #pragma unroll
        for (int i = 0; i < VQ_D / 4; i++) {
            float4 v = xp[i];
            s = fmaf(v.x, v.x, s); s = fmaf(v.y, v.y, s);
            s = fmaf(v.z, v.z, s); s = fmaf(v.w, v.w, s);
        }
        s_Sx[tid] = s;
    }

    // ---- A fragments: warp's 32 rows as two m16 tiles, bf16 in regs ----
    uint32_t afr0[4][4], afr1[4][4];
    {
        const float* xa = x + (size_t)(rowbase + r0) * VQ_D;
        const float* xb = xa + 8 * VQ_D;
        const float* xc = xa + 16 * VQ_D;
        const float* xd = xa + 24 * VQ_D;
        #pragma unroll
        for (int kt = 0; kt < 4; kt++) {
            int c = kt * 16 + 2 * tg;
            afr0[kt][0] = pack_bf16x2(xa[c],     xa[c + 1]);
            afr0[kt][1] = pack_bf16x2(xb[c],     xb[c + 1]);
            afr0[kt][2] = pack_bf16x2(xa[c + 8], xa[c + 9]);
            afr0[kt][3] = pack_bf16x2(xb[c + 8], xb[c + 9]);
            afr1[kt][0] = pack_bf16x2(xc[c],     xc[c + 1]);
            afr1[kt][1] = pack_bf16x2(xd[c],     xd[c + 1]);
            afr1[kt][2] = pack_bf16x2(xc[c + 8], xc[c + 9]);
            afr1[kt][3] = pack_bf16x2(xd[c + 8], xd[c + 9]);
        }
    }

    const uint32_t s_base   = (uint32_t)__cvta_generic_to_shared(s_stage);
    const uint32_t lds_lane = (uint32_t)((lane & 7) * VQ_EPAD * 2 + (lane >> 3) * 16);
    __syncthreads();

    // ========== SINGLE SWEEP: mma + unconditional group minima ==========
    copy_chunk(0, s_base, tid);
    #pragma unroll 1
    for (int ch = 0; ch < VQ_NCHUNK; ch++) {
        if (ch + 1 < VQ_NCHUNK) { copy_chunk(ch + 1, s_base, tid); cp_wait1(); }
        else                    { cp_wait0(); }
        __syncthreads();
        const uint32_t stage = s_base + (uint32_t)((ch & 1) * VQ_CHUNK_B);
        #pragma unroll
        for (int gq = 0; gq < 2; gq++) {            // 2 groups of 64 per chunk
            float gm0 = 3.0e38f, gm1 = 3.0e38f, gm2 = 3.0e38f, gm3 = 3.0e38f;
            #pragma unroll
            for (int j = 0; j < 8; j++) {           // 8 tiles per group
                const int nt = gq * 8 + j;
                uint32_t base = stage + (uint32_t)(nt * 8 * VQ_EPAD * 2) + lds_lane;
                uint32_t b0, b1, b2, b3, b4, b5, b6, b7;
                ldsm_x4(b0, b1, b2, b3, base);
                ldsm_x4(b4, b5, b6, b7, base + 64);
                float cA0 = 0.f, cA1 = 0.f, cA2 = 0.f, cA3 = 0.f;
                float cB0 = 0.f, cB1 = 0.f, cB2 = 0.f, cB3 = 0.f;
                float cC0 = 0.f, cC1 = 0.f, cC2 = 0.f, cC3 = 0.f;
                float cD0 = 0.f, cD1 = 0.f, cD2 = 0.f, cD3 = 0.f;
                mma_bf16(cA0, cA1, cA2, cA3, afr0[0][0], afr0[0][1], afr0[0][2], afr0[0][3], b0, b1);
                mma_bf16(cB0, cB1, cB2, cB3, afr0[2][0], afr0[2][1], afr0[2][2], afr0[2][3], b4, b5);
                mma_bf16(cC0, cC1, cC2, cC3, afr1[0][0], afr1[0][1], afr1[0][2], afr1[0][3], b0, b1);
                mma_bf16(cD0, cD1, cD2, cD3, afr1[2][0], afr1[2][1], afr1[2][2], afr1[2][3], b4, b5);
                mma_bf16(cA0, cA1, cA2, cA3, afr0[1][0], afr0[1][1], afr0[1][2], afr0[1][3], b2, b3);
                mma_bf16(cB0, cB1, cB2, cB3, afr0[3][0], afr0[3][1], afr0[3][2], afr0[3][3], b6, b7);
                mma_bf16(cC0, cC1, cC2, cC3, afr1[1][0], afr1[1][1], afr1[1][2], afr1[1][3], b2, b3);
                mma_bf16(cD0, cD1, cD2, cD3, afr1[3][0], afr1[3][1], afr1[3][2], afr1[3][3], b6, b7);
                float2 se = *reinterpret_cast<const float2*>(&s_Se[ch * VQ_CHUNK + nt * 8 + 2 * tg]);
                float d00 = fmaf(-2.f, cA0, fmaf(-2.f, cB0, se.x));
                float d01 = fmaf(-2.f, cA1, fmaf(-2.f, cB1, se.y));
                float d10 = fmaf(-2.f, cA2, fmaf(-2.f, cB2, se.x));
                float d11 = fmaf(-2.f, cA3, fmaf(-2.f, cB3, se.y));
                float d20 = fmaf(-2.f, cC0, fmaf(-2.f, cD0, se.x));
                float d21 = fmaf(-2.f, cC1, fmaf(-2.f, cD1, se.y));
                float d30 = fmaf(-2.f, cC2, fmaf(-2.f, cD2, se.x));
                float d31 = fmaf(-2.f, cC3, fmaf(-2.f, cD3, se.y));
                gm0 = fminf(gm0, fminf(d00, d01));
                gm1 = fminf(gm1, fminf(d10, d11));
                gm2 = fminf(gm2, fminf(d20, d21));
                gm3 = fminf(gm3, fminf(d30, d31));
            }
            // unconditional group fold: 2 shfl per row + 1 STS (tg==0)
            gm0 = fminf(gm0, __shfl_xor_sync(0xffffffffu, gm0, 1));
            gm0 = fminf(gm0, __shfl_xor_sync(0xffffffffu, gm0, 2));
            gm1 = fminf(gm1, __shfl_xor_sync(0xffffffffu, gm1, 1));
            gm1 = fminf(gm1, __shfl_xor_sync(0xffffffffu, gm1, 2));
            gm2 = fminf(gm2, __shfl_xor_sync(0xffffffffu, gm2, 1));
            gm2 = fminf(gm2, __shfl_xor_sync(0xffffffffu, gm2, 2));
            gm3 = fminf(gm3, __shfl_xor_sync(0xffffffffu, gm3, 1));
            gm3 = fminf(gm3, __shfl_xor_sync(0xffffffffu, gm3, 2));
            const int grp = ch * 2 + gq;
            if (tg == 0) {
                s_gmin[grp][r0] = gm0;
                s_gmin[grp][r1] = gm1;
                s_gmin[grp][r2] = gm2;
                s_gmin[grp][r3] = gm3;
            }
        }
        __syncthreads();
    }

    // ===== warp-cooperative exact rescore: warp per row, lane per code =====
    {
        const unsigned full = 0xffffffffu;
        #pragma unroll 1
        for (int rr = 0; rr < 32; rr++) {
            const int r   = wid * 32 + rr;
            const int row = rowbase + r;
            // lane l holds group (l & 15)'s min; lanes 16-31 duplicate
            float gm = s_gmin[lane & 15][r];
            float rowmin = gm;
            #pragma unroll
            for (int o = 16; o > 0; o >>= 1)
                rowmin = fminf(rowmin, __shfl_xor_sync(full, rowmin, o));
            const float thr = rowmin + VQ_MARGIN;
            unsigned mask = __ballot_sync(full, gm <= thr) & 0xFFFFu;

            const float Sx = s_Sx[r];
            const float4* xp = reinterpret_cast<const float4*>(x + (size_t)row * VQ_D);

            float best = 3.0e38f;
            int   bidx = VQ_K;
            while (mask) {
                const int grp = __ffs(mask) - 1;
                mask &= mask - 1;
                const int k1 = grp * VQ_GRP + lane;        // codes grp*64 + lane
                const int k2 = k1 + 32;                    // and + 32
                float da = exact_dist_stream(xp, Sx, cb, s_Se, k1);
                float db = exact_dist_stream(xp, Sx, cb, s_Se, k2);
                if (da < best || (da == best && k1 < bidx)) { best = da; bidx = k1; }
                if (db < best || (db == best && k2 < bidx)) { best = db; bidx = k2; }
            }
            #pragma unroll
            for (int o = 16; o > 0; o >>= 1) {
                float od = __shfl_xor_sync(full, best, o);
                int   oi = __shfl_xor_sync(full, bidx, o);
                if (od < best || (od == best && oi < bidx)) { best = od; bidx = oi; }
            }
            if (lane == 0) s_win[r] = bidx;
        }
    }
    __syncthreads();

    // ===== output + per-row loss (thread per row) =====
    float rl = 0.0f;
    {
        const int row = rowbase + tid;
        const int win = s_win[tid];
        const float4* xp = reinterpret_cast<const float4*>(x + (size_t)row * VQ_D);
        const float4* qp = reinterpret_cast<const float4*>(cb + (size_t)win * VQ_D);
        float4* op = reinterpret_cast<float4*>(out + (size_t)row * VQ_D);
        #pragma unroll
        for (int i = 0; i < VQ_D / 4; i++) {
            float4 q = qp[i], xv = xp[i];
            float rx = q.x - xv.x, ry = q.y - xv.y, rz = q.z - xv.z, rw = q.w - xv.w;
            if (write_q) {
                float4 o; o.x = xv.x + rx; o.y = xv.y + ry; o.z = xv.z + rz; o.w = xv.w + rw;
                op[i] = o;
            }
            rl = fmaf(rx, rx, rl); rl = fmaf(ry, ry, rl);
            rl = fmaf(rz, rz, rl); rl = fmaf(rw, rw, rl);
        }
    }
    s_red[tid] = rl;
    __syncthreads();
    #pragma unroll
    for (int s = VQ_TPB / 2; s > 0; s >>= 1) {
        if (tid < s) s_red[tid] += s_red[tid + s];
        __syncthreads();
    }

    // ===== fused loss: last-block ticket (deterministic, replay-safe) =====
    if (tid == 0) {
        g_vq_partial[blockIdx.x] = s_red[0];
        __threadfence();
        unsigned int t = atomicAdd(&g_vq_ticket, 1u);
        s_last = (t == VQ_GRID - 1) ? 1 : 0;
    }
    __syncthreads();
    if (s_last) {
        __threadfence();
        double acc = 0.0;
        for (int i = tid; i < VQ_GRID; i += VQ_TPB)
            acc += (double)g_vq_partial[i];
        s_dred[tid] = acc;
        __syncthreads();
        #pragma unroll
        for (int s = VQ_TPB / 2; s > 0; s >>= 1) {
            if (tid < s) s_dred[tid] += s_dred[tid + s];
            __syncthreads();
        }
        if (tid == 0) {
            double m = s_dred[0] / (double)((size_t)VQ_N * VQ_D);
            float loss = (float)(1.25 * m);
            const long long nq = (long long)VQ_N * VQ_D;
            if (out_size > nq) {
                for (long long i = nq; i < out_size; i++) out[i] = loss;
            } else if (out_size < nq && out_size > 0) {
                out[0] = loss;
            }
            g_vq_ticket = 0;
        }
    }
}

extern "C" void kernel_launch(void* const* d_in, const int* in_sizes, int n_in,
                              void* d_out, int out_size)
{
    const float* x  = (const float*)d_in[0];
    const float* cb = (const float*)d_in[1];
    float* out = (float*)d_out;

    const long long nq = (long long)VQ_N * VQ_D;
    int write_q = (out_size >= nq) ? 1 : 0;

    static int smem_configured = 0;
    if (!smem_configured) {
        cudaFuncSetAttribute(vq_main_kernel,
                             cudaFuncAttributeMaxDynamicSharedMemorySize, VQ_SMEM_E);
        smem_configured = 1;
    }

    vq_prep_kernel<<<VQ_K / VQ_TPB, VQ_TPB>>>(cb);
    vq_main_kernel<<<VQ_GRID, VQ_TPB, VQ_SMEM_E>>>(x, cb, out, write_q,
                                                   (long long)out_size);
}